// round 9
// baseline (speedup 1.0000x reference)
#include <cuda_runtime.h>
#include <cstdint>

#define ROW_LEN 2048
#define NTHREADS 256
#define NWARP 8
#define VPT 8
#define K_TOP 64
#define NBINS 512
#define FSCALE 56.0f
#define FBIAS  256.0f
#define FULLMASK 0xffffffffu

__global__ __launch_bounds__(NTHREADS, 8)   // cap regs at 32 -> 8 CTAs/SM
void topk_softmax_kernel(const float* __restrict__ in, float* __restrict__ out) {
    const int tid  = threadIdx.x;
    const int lane = tid & 31;
    const int wid  = tid >> 5;
    const size_t rbase = (size_t)blockIdx.x * ROW_LEN;

    const float4* rp4 = reinterpret_cast<const float4*>(in + rbase);
    float4*       op4 = reinterpret_cast<float4*>(out + rbase);

    __shared__ int   hist[NBINS];
    __shared__ float cand[ROW_LEN];      // crossing-bin candidates (worst-case safe)
    __shared__ int   s_wsum[NWARP];
    __shared__ int   s_bin, s_kc, s_cnt;
    __shared__ float s_sum;

    // ---- 1. Issue loads; zero histogram while they're in flight ----
    float4 a = rp4[tid];
    float4 b = rp4[tid + NTHREADS];
    reinterpret_cast<int2*>(hist)[tid] = make_int2(0, 0);
    if (tid == 0) { s_cnt = 0; s_sum = 0.0f; }

    float v[VPT];
    v[0] = a.x; v[1] = a.y; v[2] = a.z; v[3] = a.w;
    v[4] = b.x; v[5] = b.y; v[6] = b.z; v[7] = b.w;
    __syncthreads();                                          // B1

    // ---- 2. Single value-domain histogram (512 uniform bins) ----
    #pragma unroll
    for (int i = 0; i < VPT; i++) {
        int bi = (int)fmaf(v[i], FSCALE, FBIAS);
        bi = min(max(bi, 0), NBINS - 1);
        atomicAdd(&hist[bi], 1);
    }
    __syncthreads();                                          // B2

    // ---- 3. Suffix scan; thread t owns bins (2t, 2t+1) ----
    const int2 h = reinterpret_cast<int2*>(hist)[tid];
    const int lsum = h.x + h.y;
    int s = lsum;                                 // warp suffix incl. self
    #pragma unroll
    for (int o = 1; o < 32; o <<= 1) {
        int t = __shfl_down_sync(FULLMASK, s, o);
        if (lane + o < 32) s += t;
    }
    if (lane == 0) s_wsum[wid] = s;
    __syncthreads();                                          // B3

    int T = s - lsum;                             // count in bins strictly above my pair
    #pragma unroll
    for (int w = 1; w < NWARP; w++)
        if (w > wid) T += s_wsum[w];

    if (T < K_TOP && T + lsum >= K_TOP) {         // unique thread owns the crossing
        const int nsuf = T + h.y;                 // bin 2t+1 is the higher bin
        if (nsuf >= K_TOP) {
            s_bin = tid * 2 + 1;
            s_kc  = K_TOP - T;
        } else {
            s_bin = tid * 2;
            s_kc  = K_TOP - nsuf;
        }
    }
    __syncthreads();                                          // B4

    // ---- 4. Compact the crossing bin's elements ----
    const int bstar = s_bin;
    const int kc    = s_kc;
    const float flo = (bstar == 0)         ? -__int_as_float(0x7f800000) : (float)bstar;
    const float fhi = (bstar == NBINS - 1) ?  __int_as_float(0x7f800000) : (float)(bstar + 1);
    #pragma unroll
    for (int i = 0; i < VPT; i++) {
        float f = fmaf(v[i], FSCALE, FBIAS);      // identical FMA as binning
        if (f >= flo && f < fhi) {
            int idx = atomicAdd(&s_cnt, 1);
            cand[idx] = v[i];
        }
    }
    __syncthreads();                                          // B5

    // ---- 5. ALL warps redundantly find the kc-th largest candidate ----
    // (removes a broadcast barrier; candidates ~2-3, loop runs ~once)
    float vk;
    {
        const int c = s_cnt;
        int   remaining = kc;
        float bound = __int_as_float(0x7f800000); // +inf
        for (;;) {
            float m = -__int_as_float(0x7f800000);
            for (int i = lane; i < c; i += 32) {
                float x = cand[i];
                if (x < bound) m = fmaxf(m, x);
            }
            #pragma unroll
            for (int o = 16; o; o >>= 1) m = fmaxf(m, __shfl_xor_sync(FULLMASK, m, o));
            int cnt = 0;
            for (int i = lane; i < c; i += 32) cnt += (cand[i] == m);
            #pragma unroll
            for (int o = 16; o; o >>= 1) cnt += __shfl_xor_sync(FULLMASK, cnt, o);
            if (cnt >= remaining) { vk = m; break; }
            remaining -= cnt;
            bound = m;
        }
    }

    // ---- 6. Masked exp + sum (offset by vk; softmax is shift-invariant) ----
    float sum = 0.0f;
    #pragma unroll
    for (int i = 0; i < VPT; i++) {
        float ev = (v[i] >= vk) ? __expf(v[i] - vk) : 0.0f;
        v[i] = ev;
        sum += ev;
    }
    #pragma unroll
    for (int o = 16; o; o >>= 1) sum += __shfl_xor_sync(FULLMASK, sum, o);
    if (lane == 0) atomicAdd(&s_sum, sum);
    __syncthreads();                                          // B6

    const float inv = __fdividef(1.0f, s_sum);

    // ---- 7. Store (coalesced float4) ----
    float4 o1 = make_float4(v[0] * inv, v[1] * inv, v[2] * inv, v[3] * inv);
    float4 o2 = make_float4(v[4] * inv, v[5] * inv, v[6] * inv, v[7] * inv);
    op4[tid]            = o1;
    op4[tid + NTHREADS] = o2;
}

extern "C" void kernel_launch(void* const* d_in, const int* in_sizes, int n_in,
                              void* d_out, int out_size) {
    const float* in  = (const float*)d_in[0];
    float*       out = (float*)d_out;
    const int nrows = in_sizes[0] / ROW_LEN;   // 2*16*2048 = 65536
    topk_softmax_kernel<<<nrows, NTHREADS>>>(in, out);
}

// round 10
// speedup vs baseline: 1.1692x; 1.1692x over previous
#include <cuda_runtime.h>
#include <cstdint>

#define ROW_LEN 2048
#define NTHREADS 256
#define NWARP 8
#define VPT 8
#define K_TOP 64
#define NBINS 512
#define FSCALE 56.0f
#define FBIAS  256.0f
#define FULLMASK 0xffffffffu

__global__ __launch_bounds__(NTHREADS, 8)   // cap regs at 32 -> 8 CTAs/SM
void topk_softmax_kernel(const float* __restrict__ in, float* __restrict__ out) {
    const int tid  = threadIdx.x;
    const int lane = tid & 31;
    const int wid  = tid >> 5;
    const size_t rbase = (size_t)blockIdx.x * ROW_LEN;

    const float4* rp4 = reinterpret_cast<const float4*>(in + rbase);
    float4*       op4 = reinterpret_cast<float4*>(out + rbase);

    __shared__ int   hist[NBINS];
    __shared__ float cand[ROW_LEN];      // crossing-bin candidates (worst-case safe)
    __shared__ int   s_wsum[NWARP];
    __shared__ int   s_bin, s_kc, s_cnt;
    __shared__ float s_vk, s_sum;

    // ---- 1. Issue loads; zero histogram while they're in flight ----
    float4 a = rp4[tid];
    float4 b = rp4[tid + NTHREADS];
    reinterpret_cast<int2*>(hist)[tid] = make_int2(0, 0);
    if (tid == 0) { s_cnt = 0; s_sum = 0.0f; }

    float v[VPT];
    v[0] = a.x; v[1] = a.y; v[2] = a.z; v[3] = a.w;
    v[4] = b.x; v[5] = b.y; v[6] = b.z; v[7] = b.w;
    __syncthreads();                                          // B1

    // ---- 2. Single value-domain histogram (512 uniform bins) ----
    #pragma unroll
    for (int i = 0; i < VPT; i++) {
        int bi = (int)fmaf(v[i], FSCALE, FBIAS);
        bi = min(max(bi, 0), NBINS - 1);
        atomicAdd(&hist[bi], 1);
    }
    __syncthreads();                                          // B2

    // ---- 3. Suffix scan; thread t owns bins (2t, 2t+1) ----
    const int2 h = reinterpret_cast<int2*>(hist)[tid];
    const int lsum = h.x + h.y;
    int s = lsum;                                 // warp suffix incl. self
    #pragma unroll
    for (int o = 1; o < 32; o <<= 1) {
        int t = __shfl_down_sync(FULLMASK, s, o);
        if (lane + o < 32) s += t;
    }
    if (lane == 0) s_wsum[wid] = s;
    __syncthreads();                                          // B3

    int T = s - lsum;                             // count in bins strictly above my pair
    #pragma unroll
    for (int w = 1; w < NWARP; w++)
        if (w > wid) T += s_wsum[w];

    if (T < K_TOP && T + lsum >= K_TOP) {         // unique thread owns the crossing
        const int nsuf = T + h.y;                 // bin 2t+1 is the higher bin
        if (nsuf >= K_TOP) {
            s_bin = tid * 2 + 1;
            s_kc  = K_TOP - T;
        } else {
            s_bin = tid * 2;
            s_kc  = K_TOP - nsuf;
        }
    }
    __syncthreads();                                          // B4

    // ---- 4. Compact the crossing bin's elements ----
    const int bstar = s_bin;
    const int kc    = s_kc;
    const float flo = (bstar == 0)         ? -__int_as_float(0x7f800000) : (float)bstar;
    const float fhi = (bstar == NBINS - 1) ?  __int_as_float(0x7f800000) : (float)(bstar + 1);
    #pragma unroll
    for (int i = 0; i < VPT; i++) {
        float f = fmaf(v[i], FSCALE, FBIAS);      // identical FMA as binning
        if (f >= flo && f < fhi) {
            int idx = atomicAdd(&s_cnt, 1);
            cand[idx] = v[i];
        }
    }
    __syncthreads();                                          // B5

    // ---- 5. Warp 0 only: exact kc-th largest among candidates (tie-robust) ----
    if (wid == 0) {
        const int c = s_cnt;                      // usually ~2-3
        int   remaining = kc;
        float bound = __int_as_float(0x7f800000); // +inf
        float vk;
        for (;;) {
            float m = -__int_as_float(0x7f800000);
            for (int i = lane; i < c; i += 32) {
                float x = cand[i];
                if (x < bound) m = fmaxf(m, x);
            }
            #pragma unroll
            for (int o = 16; o; o >>= 1) m = fmaxf(m, __shfl_xor_sync(FULLMASK, m, o));
            int cnt = 0;
            for (int i = lane; i < c; i += 32) cnt += (cand[i] == m);
            #pragma unroll
            for (int o = 16; o; o >>= 1) cnt += __shfl_xor_sync(FULLMASK, cnt, o);
            if (cnt >= remaining) { vk = m; break; }
            remaining -= cnt;
            bound = m;
        }
        if (lane == 0) s_vk = vk;
    }
    __syncthreads();                                          // B6

    // ---- 6. Masked exp + sum (offset by vk; softmax is shift-invariant) ----
    const float vk = s_vk;
    float sum = 0.0f;
    #pragma unroll
    for (int i = 0; i < VPT; i++) {
        float ev = (v[i] >= vk) ? __expf(v[i] - vk) : 0.0f;
        v[i] = ev;
        sum += ev;
    }
    #pragma unroll
    for (int o = 16; o; o >>= 1) sum += __shfl_xor_sync(FULLMASK, sum, o);
    if (lane == 0) atomicAdd(&s_sum, sum);
    __syncthreads();                                          // B7

    const float inv = __fdividef(1.0f, s_sum);

    // ---- 7. Store (coalesced float4) ----
    float4 o1 = make_float4(v[0] * inv, v[1] * inv, v[2] * inv, v[3] * inv);
    float4 o2 = make_float4(v[4] * inv, v[5] * inv, v[6] * inv, v[7] * inv);
    op4[tid]            = o1;
    op4[tid + NTHREADS] = o2;
}

extern "C" void kernel_launch(void* const* d_in, const int* in_sizes, int n_in,
                              void* d_out, int out_size) {
    const float* in  = (const float*)d_in[0];
    float*       out = (float*)d_out;
    const int nrows = in_sizes[0] / ROW_LEN;   // 2*16*2048 = 65536
    topk_softmax_kernel<<<nrows, NTHREADS>>>(in, out);
}